// round 6
// baseline (speedup 1.0000x reference)
#include <cuda_runtime.h>

// Problem constants
#define BB 8
#define NN 5000
#define EE 40000
#define FF 64
#define FEE 16
#define FIL 96
#define BN (BB*NN)      // 40000
#define BE (BB*EE)      // 320000
#define UPD_ELEMS (BN*FIL)   // 3,840,000
#define MSG_ELEMS (BE*FIL)   // 30,720,000
#define LN_EPS 1e-3f

// Scratch (device globals: allocation-free per harness rules)
__device__ __align__(16) float g_Pa[UPD_ELEMS];   // nodes @ Wm[0:64]
__device__ __align__(16) float g_Pb[UPD_ELEMS];   // nodes @ Wm[64:128]
__device__ __align__(16) float g_agg[UPD_ELEMS];  // segment-sum of messages
__device__ int g_cnt[BN];        // per-node incoming-edge count
__device__ int g_off[BN + 1];    // CSR offsets (exclusive scan of g_cnt)
__device__ int g_slot[BE];       // per-edge slot within its node's list
__device__ int g_elist[BE];      // CSR edge id list

__device__ __forceinline__ float warp_sum(float v) {
#pragma unroll
    for (int o = 16; o; o >>= 1) v += __shfl_xor_sync(0xffffffffu, v, o);
    return v;
}

// ---------------------------------------------------------------------------
// CSR build step 1: zero counters.
// ---------------------------------------------------------------------------
__global__ void zero_cnt_kernel() {
    int i = blockIdx.x * 1024 + threadIdx.x;
    if (i < BN) g_cnt[i] = 0;
}

// ---------------------------------------------------------------------------
// CSR build step 2: count incoming edges per node, record each edge's slot.
// ---------------------------------------------------------------------------
__global__ __launch_bounds__(256) void count_kernel(const int* __restrict__ edges) {
    int e = blockIdx.x * 256 + threadIdx.x;   // BE divisible by 256
    int2 e2 = ((const int2*)edges)[e];
    int node = (e / EE) * NN + e2.y;          // batch * NN + dst
    g_slot[e] = atomicAdd(&g_cnt[node], 1);
}

// ---------------------------------------------------------------------------
// CSR build step 3: exclusive scan of g_cnt (single block, shuffle scan).
// ---------------------------------------------------------------------------
__global__ __launch_bounds__(1024) void scan_kernel() {
    __shared__ int wsum[32];
    __shared__ int s_base, s_tot;
    int tid = threadIdx.x, lane = tid & 31, wid = tid >> 5;
    if (tid == 0) s_base = 0;
    __syncthreads();

    for (int chunk = 0; chunk < BN; chunk += 1024) {
        int i = chunk + tid;
        int v = (i < BN) ? g_cnt[i] : 0;
        // intra-warp inclusive scan
        int incl = v;
#pragma unroll
        for (int d = 1; d < 32; d <<= 1) {
            int t = __shfl_up_sync(0xffffffffu, incl, d);
            if (lane >= d) incl += t;
        }
        if (lane == 31) wsum[wid] = incl;
        __syncthreads();
        if (wid == 0) {
            int w = wsum[lane];
            int ws = w;
#pragma unroll
            for (int d = 1; d < 32; d <<= 1) {
                int t = __shfl_up_sync(0xffffffffu, ws, d);
                if (lane >= d) ws += t;
            }
            wsum[lane] = ws - w;          // exclusive warp base
            if (lane == 31) s_tot = ws;   // chunk total
        }
        __syncthreads();
        if (i < BN) g_off[i] = s_base + wsum[wid] + (incl - v);
        __syncthreads();
        if (tid == 0) s_base += s_tot;
        __syncthreads();
    }
    if (tid == 0) g_off[BN] = BE;
}

// ---------------------------------------------------------------------------
// CSR build step 4: scatter edge ids into per-node lists.
// ---------------------------------------------------------------------------
__global__ __launch_bounds__(256) void scatter_kernel(const int* __restrict__ edges) {
    int e = blockIdx.x * 256 + threadIdx.x;
    int2 e2 = ((const int2*)edges)[e];
    int node = (e / EE) * NN + e2.y;
    g_elist[g_off[node] + g_slot[e]] = e;
}

// ---------------------------------------------------------------------------
// K1: Pa|Pb = nodes(40000x64) @ [Wm[0:64] | Wm[64:128]] (64x192)
// 64-row tile per block, 256 threads, 8x6 micro-tile, K tiled by 32.
// (round-4 proven version)
// ---------------------------------------------------------------------------
__global__ __launch_bounds__(256) void precompute_kernel(
    const float* __restrict__ nodes, const float* __restrict__ Wm) {
    __shared__ float Xs[64][32];
    __shared__ float Ws[32][192];

    int tid = threadIdx.x;
    int tx = tid & 31, ty = tid >> 5;
    int row0 = blockIdx.x * 64;

    float acc[8][6];
#pragma unroll
    for (int i = 0; i < 8; i++)
#pragma unroll
        for (int j = 0; j < 6; j++) acc[i][j] = 0.0f;

    for (int t = 0; t < 2; t++) {
        __syncthreads();
#pragma unroll
        for (int it = 0; it < 24; it++) {
            int idx = tid + 256 * it;
            int k = idx / 192, c = idx % 192;
            float v = (c < 96) ? Wm[(t * 32 + k) * FIL + c]
                               : Wm[(64 + t * 32 + k) * FIL + (c - 96)];
            Ws[k][c] = v;
        }
#pragma unroll
        for (int it = 0; it < 8; it++) {
            int idx = tid + 256 * it;
            int r = idx >> 5, c = idx & 31;
            Xs[r][c] = nodes[(row0 + r) * FF + t * 32 + c];
        }
        __syncthreads();
#pragma unroll
        for (int k = 0; k < 32; k++) {
            float xv[8], wv[6];
#pragma unroll
            for (int i = 0; i < 8; i++) xv[i] = Xs[ty + 8 * i][k];
#pragma unroll
            for (int j = 0; j < 6; j++) wv[j] = Ws[k][tx + 32 * j];
#pragma unroll
            for (int i = 0; i < 8; i++)
#pragma unroll
                for (int j = 0; j < 6; j++) acc[i][j] += xv[i] * wv[j];
        }
    }

#pragma unroll
    for (int i = 0; i < 8; i++) {
        int row = row0 + ty + 8 * i;
#pragma unroll
        for (int j = 0; j < 6; j++) {
            int c = tx + 32 * j;
            if (c < 96) g_Pa[row * FIL + c] = acc[i][j];
            else        g_Pb[row * FIL + (c - 96)] = acc[i][j];
        }
    }
}

// ---------------------------------------------------------------------------
// K2: per-edge message = LN(relu(Pa[src] + Pb[dst] + ef@WmC + bm)).
// One warp per edge. NO atomics — aggregation moved to gather_kernel.
// ---------------------------------------------------------------------------
__global__ __launch_bounds__(256) void edge_kernel(
    const float* __restrict__ ef, const int* __restrict__ edges,
    const float* __restrict__ Wm, const float* __restrict__ bm,
    const float* __restrict__ gamma, const float* __restrict__ beta,
    float* __restrict__ msg_out) {
    __shared__ float WmC[16 * 96];  // Wm rows 128..143
    __shared__ float s_bm[96], s_g[96], s_b[96];

    int tid = threadIdx.x;
    for (int i = tid; i < 16 * 96; i += 256) WmC[i] = Wm[128 * FIL + i];
    if (tid < 96) { s_bm[tid] = bm[tid]; s_g[tid] = gamma[tid]; s_b[tid] = beta[tid]; }
    __syncthreads();

    int warp = tid >> 5, lane = tid & 31;
    int eidx = blockIdx.x * 8 + warp;  // BE divisible by 8

    int b = eidx / EE;
    int2 e2 = ((const int2*)edges)[eidx];
    int src = e2.x, dst = e2.y;

    float efv = (lane < 16) ? ef[eidx * FEE + lane] : 0.0f;

    float a0 = s_bm[lane], a1 = s_bm[lane + 32], a2 = s_bm[lane + 64];
#pragma unroll
    for (int k = 0; k < 16; k++) {
        float x = __shfl_sync(0xffffffffu, efv, k);
        a0 += x * WmC[k * 96 + lane];
        a1 += x * WmC[k * 96 + lane + 32];
        a2 += x * WmC[k * 96 + lane + 64];
    }

    int pa_off = (b * NN + src) * FIL;
    int pb_off = (b * NN + dst) * FIL;
    a0 += g_Pa[pa_off + lane]      + g_Pb[pb_off + lane];
    a1 += g_Pa[pa_off + lane + 32] + g_Pb[pb_off + lane + 32];
    a2 += g_Pa[pa_off + lane + 64] + g_Pb[pb_off + lane + 64];

    a0 = fmaxf(a0, 0.0f); a1 = fmaxf(a1, 0.0f); a2 = fmaxf(a2, 0.0f);

    float mean = warp_sum(a0 + a1 + a2) * (1.0f / 96.0f);
    float d0 = a0 - mean, d1 = a1 - mean, d2 = a2 - mean;
    float var = warp_sum(d0 * d0 + d1 * d1 + d2 * d2) * (1.0f / 96.0f);
    float inv = rsqrtf(var + LN_EPS);

    int mo = eidx * FIL;
    msg_out[mo + lane]      = d0 * inv * s_g[lane]      + s_b[lane];
    msg_out[mo + lane + 32] = d1 * inv * s_g[lane + 32] + s_b[lane + 32];
    msg_out[mo + lane + 64] = d2 * inv * s_g[lane + 64] + s_b[lane + 64];
}

// ---------------------------------------------------------------------------
// K2b: gather-aggregate. One warp per node: sum messages of incoming edges
// (coalesced 128B reads from msg_out via CSR), overwrite g_agg.
// ---------------------------------------------------------------------------
__global__ __launch_bounds__(256) void gather_kernel(const float* __restrict__ msg) {
    int warp = threadIdx.x >> 5, lane = threadIdx.x & 31;
    int v = blockIdx.x * 8 + warp;   // BN divisible by 8

    int beg = g_off[v], end = g_off[v + 1];
    float a0 = 0.f, a1 = 0.f, a2 = 0.f;
    for (int j = beg; j < end; j++) {
        int e = g_elist[j];
        const float* m = msg + e * FIL;
        a0 += m[lane];
        a1 += m[lane + 32];
        a2 += m[lane + 64];
    }
    int o = v * FIL;
    g_agg[o + lane]      = a0;
    g_agg[o + lane + 32] = a1;
    g_agg[o + lane + 64] = a2;
}

// ---------------------------------------------------------------------------
// K3: updated = LN(relu([nodes | agg](40000x160) @ Wu(160x96) + bu))
// (round-4 proven version: 64-row tile, 8x3 micro-tile, fused ReLU+LN)
// ---------------------------------------------------------------------------
__global__ __launch_bounds__(256) void update_kernel(
    const float* __restrict__ nodes, const float* __restrict__ Wu,
    const float* __restrict__ bu, const float* __restrict__ gamma,
    const float* __restrict__ beta, float* __restrict__ out) {
    __shared__ float Xs[64][32];
    __shared__ float Ws[32][96];
    __shared__ float s_bu[96], s_g[96], s_b[96];

    int tid = threadIdx.x;
    int tx = tid & 31, ty = tid >> 5;
    int row0 = blockIdx.x * 64;

    if (tid < 96) { s_bu[tid] = bu[tid]; s_g[tid] = gamma[tid]; s_b[tid] = beta[tid]; }
    __syncthreads();

    float acc[8][3];
#pragma unroll
    for (int i = 0; i < 8; i++) {
        acc[i][0] = s_bu[tx];
        acc[i][1] = s_bu[tx + 32];
        acc[i][2] = s_bu[tx + 64];
    }

    for (int t = 0; t < 5; t++) {
        __syncthreads();
#pragma unroll
        for (int it = 0; it < 12; it++) {
            int idx = tid + 256 * it;
            int k = idx / 96, c = idx % 96;
            Ws[k][c] = Wu[(t * 32 + k) * FIL + c];
        }
#pragma unroll
        for (int it = 0; it < 8; it++) {
            int idx = tid + 256 * it;
            int r = idx >> 5, c = idx & 31;
            float v;
            if (t < 2) v = nodes[(row0 + r) * FF + t * 32 + c];
            else       v = g_agg[(row0 + r) * FIL + (t - 2) * 32 + c];
            Xs[r][c] = v;
        }
        __syncthreads();
#pragma unroll
        for (int k = 0; k < 32; k++) {
            float xv[8];
#pragma unroll
            for (int i = 0; i < 8; i++) xv[i] = Xs[ty + 8 * i][k];
            float w0 = Ws[k][tx], w1 = Ws[k][tx + 32], w2 = Ws[k][tx + 64];
#pragma unroll
            for (int i = 0; i < 8; i++) {
                acc[i][0] += xv[i] * w0;
                acc[i][1] += xv[i] * w1;
                acc[i][2] += xv[i] * w2;
            }
        }
    }

#pragma unroll
    for (int i = 0; i < 8; i++) {
        int row = row0 + ty + 8 * i;
        float v0 = fmaxf(acc[i][0], 0.0f);
        float v1 = fmaxf(acc[i][1], 0.0f);
        float v2 = fmaxf(acc[i][2], 0.0f);
        float mean = warp_sum(v0 + v1 + v2) * (1.0f / 96.0f);
        float d0 = v0 - mean, d1 = v1 - mean, d2 = v2 - mean;
        float var = warp_sum(d0 * d0 + d1 * d1 + d2 * d2) * (1.0f / 96.0f);
        float inv = rsqrtf(var + LN_EPS);
        int o = row * FIL;
        out[o + tx]      = d0 * inv * s_g[tx]      + s_b[tx];
        out[o + tx + 32] = d1 * inv * s_g[tx + 32] + s_b[tx + 32];
        out[o + tx + 64] = d2 * inv * s_g[tx + 64] + s_b[tx + 64];
    }
}

// ---------------------------------------------------------------------------
// Launch: CSR build + precompute -> edge messages -> gather-agg -> update.
// ---------------------------------------------------------------------------
extern "C" void kernel_launch(void* const* d_in, const int* in_sizes, int n_in,
                              void* d_out, int out_size) {
    const float* nodes = (const float*)d_in[0];
    const float* ef    = (const float*)d_in[1];
    const int*   edges = (const int*)d_in[2];
    const float* Wm    = (const float*)d_in[3];
    const float* bm    = (const float*)d_in[4];
    const float* ln_mg = (const float*)d_in[5];
    const float* ln_mb = (const float*)d_in[6];
    const float* Wu    = (const float*)d_in[7];
    const float* bu    = (const float*)d_in[8];
    const float* ln_ug = (const float*)d_in[9];
    const float* ln_ub = (const float*)d_in[10];

    float* out = (float*)d_out;
    float* upd_out = out;                  // updated_nodes first (tuple order)
    float* msg_out = out + UPD_ELEMS;      // then messages

    // CSR build (dst adjacency)
    zero_cnt_kernel<<<(BN + 1023) / 1024, 1024>>>();
    count_kernel<<<BE / 256, 256>>>(edges);
    scan_kernel<<<1, 1024>>>();
    scatter_kernel<<<BE / 256, 256>>>(edges);

    // Dense pipeline
    precompute_kernel<<<BN / 64, 256>>>(nodes, Wm);
    edge_kernel<<<BE / 8, 256>>>(ef, edges, Wm, bm, ln_mg, ln_mb, msg_out);
    gather_kernel<<<BN / 8, 256>>>(msg_out);
    update_kernel<<<BN / 64, 256>>>(nodes, Wu, bu, ln_ug, ln_ub, upd_out);
}

// round 7
// speedup vs baseline: 1.2912x; 1.2912x over previous
#include <cuda_runtime.h>

// Problem constants
#define BB 8
#define NN 5000
#define EE 40000
#define FF 64
#define FEE 16
#define FIL 96
#define BN (BB*NN)      // 40000
#define BE (BB*EE)      // 320000
#define UPD_ELEMS (BN*FIL)   // 3,840,000
#define MSG_ELEMS (BE*FIL)   // 30,720,000
#define LN_EPS 1e-3f
#define SCAN_BLK 1024
#define NSCAN ((BN + SCAN_BLK - 1) / SCAN_BLK)   // 40 blocks

// Scratch (device globals: allocation-free per harness rules)
__device__ __align__(16) float g_Pa[UPD_ELEMS];   // nodes @ Wm[0:64]
__device__ __align__(16) float g_Pb[UPD_ELEMS];   // nodes @ Wm[64:128]
__device__ __align__(16) float g_agg[UPD_ELEMS];  // segment-sum of messages
__device__ int g_cnt[BN];        // per-node incoming-edge count
__device__ int g_off[BN + 1];    // CSR offsets
__device__ int g_slot[BE];       // per-edge slot within its node's list
__device__ int g_esrc[BE];       // CSR payload: packed (eidx<<13 unused) -> store eidx and src separately
__device__ int g_eid[BE];        // CSR edge id list
__device__ int g_bsum[NSCAN];    // per-block sums for hierarchical scan

__device__ __forceinline__ float warp_sum(float v) {
#pragma unroll
    for (int o = 16; o; o >>= 1) v += __shfl_xor_sync(0xffffffffu, v, o);
    return v;
}

// ---------------------------------------------------------------------------
// CSR step 1: zero counters.
// ---------------------------------------------------------------------------
__global__ void zero_cnt_kernel() {
    int i = blockIdx.x * 1024 + threadIdx.x;
    if (i < BN) g_cnt[i] = 0;
}

// ---------------------------------------------------------------------------
// CSR step 2: count incoming edges per node, record slot.
// ---------------------------------------------------------------------------
__global__ __launch_bounds__(256) void count_kernel(const int* __restrict__ edges) {
    int e = blockIdx.x * 256 + threadIdx.x;   // BE divisible by 256
    int2 e2 = ((const int2*)edges)[e];
    int node = (e / EE) * NN + e2.y;          // batch * NN + dst
    g_slot[e] = atomicAdd(&g_cnt[node], 1);
}

// ---------------------------------------------------------------------------
// CSR step 3a: per-block scan of g_cnt -> partial offsets + block sums.
// ---------------------------------------------------------------------------
__global__ __launch_bounds__(SCAN_BLK) void scan_local_kernel() {
    __shared__ int wsum[32];
    int tid = threadIdx.x, lane = tid & 31, wid = tid >> 5;
    int i = blockIdx.x * SCAN_BLK + tid;
    int v = (i < BN) ? g_cnt[i] : 0;
    int incl = v;
#pragma unroll
    for (int d = 1; d < 32; d <<= 1) {
        int t = __shfl_up_sync(0xffffffffu, incl, d);
        if (lane >= d) incl += t;
    }
    if (lane == 31) wsum[wid] = incl;
    __syncthreads();
    if (wid == 0) {
        int w = wsum[lane];
        int ws = w;
#pragma unroll
        for (int d = 1; d < 32; d <<= 1) {
            int t = __shfl_up_sync(0xffffffffu, ws, d);
            if (lane >= d) ws += t;
        }
        wsum[lane] = ws - w;
        if (lane == 31) g_bsum[blockIdx.x] = ws;
    }
    __syncthreads();
    if (i < BN) g_off[i] = wsum[wid] + (incl - v);   // block-local exclusive
}

// ---------------------------------------------------------------------------
// CSR step 3b: scan the 40 block sums (one warp).
// ---------------------------------------------------------------------------
__global__ void scan_bsum_kernel() {
    int lane = threadIdx.x;   // 64 threads, NSCAN=40
    int v = (lane < NSCAN) ? g_bsum[lane] : 0;
    // simple serial-free scan via shared
    __shared__ int s[64];
    s[lane] = v;
    __syncthreads();
    int acc = 0;
    for (int j = 0; j < lane && j < NSCAN; j++) acc += s[j];
    if (lane < NSCAN) g_bsum[lane] = acc;
    if (lane == 0) g_off[BN] = BE;
}

// ---------------------------------------------------------------------------
// CSR step 3c: add block bases.
// ---------------------------------------------------------------------------
__global__ __launch_bounds__(SCAN_BLK) void scan_add_kernel() {
    int i = blockIdx.x * SCAN_BLK + threadIdx.x;
    if (i < BN) g_off[i] += g_bsum[blockIdx.x];
}

// ---------------------------------------------------------------------------
// CSR step 4: scatter edge ids + src into per-node lists.
// ---------------------------------------------------------------------------
__global__ __launch_bounds__(256) void scatter_kernel(const int* __restrict__ edges) {
    int e = blockIdx.x * 256 + threadIdx.x;
    int2 e2 = ((const int2*)edges)[e];
    int node = (e / EE) * NN + e2.y;
    int p = g_off[node] + g_slot[e];
    g_eid[p] = e;
    g_esrc[p] = e2.x;
}

// ---------------------------------------------------------------------------
// K1: Pa|Pb = nodes(40000x64) @ [Wm[0:64] | Wm[64:128]] (64x192)
// (round-4 proven version)
// ---------------------------------------------------------------------------
__global__ __launch_bounds__(256) void precompute_kernel(
    const float* __restrict__ nodes, const float* __restrict__ Wm) {
    __shared__ float Xs[64][32];
    __shared__ float Ws[32][192];

    int tid = threadIdx.x;
    int tx = tid & 31, ty = tid >> 5;
    int row0 = blockIdx.x * 64;

    float acc[8][6];
#pragma unroll
    for (int i = 0; i < 8; i++)
#pragma unroll
        for (int j = 0; j < 6; j++) acc[i][j] = 0.0f;

    for (int t = 0; t < 2; t++) {
        __syncthreads();
#pragma unroll
        for (int it = 0; it < 24; it++) {
            int idx = tid + 256 * it;
            int k = idx / 192, c = idx % 192;
            float v = (c < 96) ? Wm[(t * 32 + k) * FIL + c]
                               : Wm[(64 + t * 32 + k) * FIL + (c - 96)];
            Ws[k][c] = v;
        }
#pragma unroll
        for (int it = 0; it < 8; it++) {
            int idx = tid + 256 * it;
            int r = idx >> 5, c = idx & 31;
            Xs[r][c] = nodes[(row0 + r) * FF + t * 32 + c];
        }
        __syncthreads();
#pragma unroll
        for (int k = 0; k < 32; k++) {
            float xv[8], wv[6];
#pragma unroll
            for (int i = 0; i < 8; i++) xv[i] = Xs[ty + 8 * i][k];
#pragma unroll
            for (int j = 0; j < 6; j++) wv[j] = Ws[k][tx + 32 * j];
#pragma unroll
            for (int i = 0; i < 8; i++)
#pragma unroll
                for (int j = 0; j < 6; j++) acc[i][j] += xv[i] * wv[j];
        }
    }

#pragma unroll
    for (int i = 0; i < 8; i++) {
        int row = row0 + ty + 8 * i;
#pragma unroll
        for (int j = 0; j < 6; j++) {
            int c = tx + 32 * j;
            if (c < 96) g_Pa[row * FIL + c] = acc[i][j];
            else        g_Pb[row * FIL + (c - 96)] = acc[i][j];
        }
    }
}

// ---------------------------------------------------------------------------
// K2 (fused): warp per destination node. For each incoming edge: compute
// message = LN(relu(Pa[src] + Pb[node] + ef@WmC + bm)), write it to msg_out,
// and accumulate into registers; single store to g_agg. No atomics; Pb read
// once per node; edge ids batch-loaded one-per-lane and broadcast via shfl.
// ---------------------------------------------------------------------------
__global__ __launch_bounds__(256) void node_msg_kernel(
    const float* __restrict__ ef, const float* __restrict__ Wm,
    const float* __restrict__ bm, const float* __restrict__ gamma,
    const float* __restrict__ beta, float* __restrict__ msg_out) {
    __shared__ float WmC[16 * 96];  // Wm rows 128..143
    __shared__ float s_bm[96], s_g[96], s_b[96];

    int tid = threadIdx.x;
    for (int i = tid; i < 16 * 96; i += 256) WmC[i] = Wm[128 * FIL + i];
    if (tid < 96) { s_bm[tid] = bm[tid]; s_g[tid] = gamma[tid]; s_b[tid] = beta[tid]; }
    __syncthreads();

    int warp = tid >> 5, lane = tid & 31;
    int v = blockIdx.x * 8 + warp;   // BN divisible by 8
    int base = (v / NN) * NN;        // batch * NN

    int beg = g_off[v], end = g_off[v + 1];

    // Pb for this node, once.
    float pb0 = g_Pb[v * FIL + lane];
    float pb1 = g_Pb[v * FIL + lane + 32];
    float pb2 = g_Pb[v * FIL + lane + 64];

    float acc0 = 0.f, acc1 = 0.f, acc2 = 0.f;

    for (int c0 = beg; c0 < end; c0 += 32) {
        int m = min(32, end - c0);
        int e_l   = (lane < m) ? g_eid[c0 + lane]  : 0;
        int src_l = (lane < m) ? g_esrc[c0 + lane] : 0;

        for (int j = 0; j < m; j++) {
            int ej   = __shfl_sync(0xffffffffu, e_l, j);
            int srcj = __shfl_sync(0xffffffffu, src_l, j);

            float efv = (lane < 16) ? ef[ej * FEE + lane] : 0.0f;

            float a0 = s_bm[lane], a1 = s_bm[lane + 32], a2 = s_bm[lane + 64];
#pragma unroll
            for (int k = 0; k < 16; k++) {
                float x = __shfl_sync(0xffffffffu, efv, k);
                a0 += x * WmC[k * 96 + lane];
                a1 += x * WmC[k * 96 + lane + 32];
                a2 += x * WmC[k * 96 + lane + 64];
            }

            int pa_off = (base + srcj) * FIL;
            a0 += g_Pa[pa_off + lane]      + pb0;
            a1 += g_Pa[pa_off + lane + 32] + pb1;
            a2 += g_Pa[pa_off + lane + 64] + pb2;

            a0 = fmaxf(a0, 0.0f); a1 = fmaxf(a1, 0.0f); a2 = fmaxf(a2, 0.0f);

            float mean = warp_sum(a0 + a1 + a2) * (1.0f / 96.0f);
            float d0 = a0 - mean, d1 = a1 - mean, d2 = a2 - mean;
            float var = warp_sum(d0 * d0 + d1 * d1 + d2 * d2) * (1.0f / 96.0f);
            float inv = rsqrtf(var + LN_EPS);

            float y0 = d0 * inv * s_g[lane]      + s_b[lane];
            float y1 = d1 * inv * s_g[lane + 32] + s_b[lane + 32];
            float y2 = d2 * inv * s_g[lane + 64] + s_b[lane + 64];

            int mo = ej * FIL;
            msg_out[mo + lane]      = y0;
            msg_out[mo + lane + 32] = y1;
            msg_out[mo + lane + 64] = y2;

            acc0 += y0; acc1 += y1; acc2 += y2;
        }
    }

    int o = v * FIL;
    g_agg[o + lane]      = acc0;
    g_agg[o + lane + 32] = acc1;
    g_agg[o + lane + 64] = acc2;
}

// ---------------------------------------------------------------------------
// K3: updated = LN(relu([nodes | agg](40000x160) @ Wu(160x96) + bu))
// (round-4 proven version)
// ---------------------------------------------------------------------------
__global__ __launch_bounds__(256) void update_kernel(
    const float* __restrict__ nodes, const float* __restrict__ Wu,
    const float* __restrict__ bu, const float* __restrict__ gamma,
    const float* __restrict__ beta, float* __restrict__ out) {
    __shared__ float Xs[64][32];
    __shared__ float Ws[32][96];
    __shared__ float s_bu[96], s_g[96], s_b[96];

    int tid = threadIdx.x;
    int tx = tid & 31, ty = tid >> 5;
    int row0 = blockIdx.x * 64;

    if (tid < 96) { s_bu[tid] = bu[tid]; s_g[tid] = gamma[tid]; s_b[tid] = beta[tid]; }
    __syncthreads();

    float acc[8][3];
#pragma unroll
    for (int i = 0; i < 8; i++) {
        acc[i][0] = s_bu[tx];
        acc[i][1] = s_bu[tx + 32];
        acc[i][2] = s_bu[tx + 64];
    }

    for (int t = 0; t < 5; t++) {
        __syncthreads();
#pragma unroll
        for (int it = 0; it < 12; it++) {
            int idx = tid + 256 * it;
            int k = idx / 96, c = idx % 96;
            Ws[k][c] = Wu[(t * 32 + k) * FIL + c];
        }
#pragma unroll
        for (int it = 0; it < 8; it++) {
            int idx = tid + 256 * it;
            int r = idx >> 5, c = idx & 31;
            float v;
            if (t < 2) v = nodes[(row0 + r) * FF + t * 32 + c];
            else       v = g_agg[(row0 + r) * FIL + (t - 2) * 32 + c];
            Xs[r][c] = v;
        }
        __syncthreads();
#pragma unroll
        for (int k = 0; k < 32; k++) {
            float xv[8];
#pragma unroll
            for (int i = 0; i < 8; i++) xv[i] = Xs[ty + 8 * i][k];
            float w0 = Ws[k][tx], w1 = Ws[k][tx + 32], w2 = Ws[k][tx + 64];
#pragma unroll
            for (int i = 0; i < 8; i++) {
                acc[i][0] += xv[i] * w0;
                acc[i][1] += xv[i] * w1;
                acc[i][2] += xv[i] * w2;
            }
        }
    }

#pragma unroll
    for (int i = 0; i < 8; i++) {
        int row = row0 + ty + 8 * i;
        float v0 = fmaxf(acc[i][0], 0.0f);
        float v1 = fmaxf(acc[i][1], 0.0f);
        float v2 = fmaxf(acc[i][2], 0.0f);
        float mean = warp_sum(v0 + v1 + v2) * (1.0f / 96.0f);
        float d0 = v0 - mean, d1 = v1 - mean, d2 = v2 - mean;
        float var = warp_sum(d0 * d0 + d1 * d1 + d2 * d2) * (1.0f / 96.0f);
        float inv = rsqrtf(var + LN_EPS);
        int o = row * FIL;
        out[o + tx]      = d0 * inv * s_g[tx]      + s_b[tx];
        out[o + tx + 32] = d1 * inv * s_g[tx + 32] + s_b[tx + 32];
        out[o + tx + 64] = d2 * inv * s_g[tx + 64] + s_b[tx + 64];
    }
}

// ---------------------------------------------------------------------------
// Launch: CSR build || precompute -> fused node/message kernel -> update.
// ---------------------------------------------------------------------------
extern "C" void kernel_launch(void* const* d_in, const int* in_sizes, int n_in,
                              void* d_out, int out_size) {
    const float* nodes = (const float*)d_in[0];
    const float* ef    = (const float*)d_in[1];
    const int*   edges = (const int*)d_in[2];
    const float* Wm    = (const float*)d_in[3];
    const float* bm    = (const float*)d_in[4];
    const float* ln_mg = (const float*)d_in[5];
    const float* ln_mb = (const float*)d_in[6];
    const float* Wu    = (const float*)d_in[7];
    const float* bu    = (const float*)d_in[8];
    const float* ln_ug = (const float*)d_in[9];
    const float* ln_ub = (const float*)d_in[10];

    float* out = (float*)d_out;
    float* upd_out = out;                  // updated_nodes first (tuple order)
    float* msg_out = out + UPD_ELEMS;      // then messages

    // CSR build (dst adjacency), hierarchical scan
    zero_cnt_kernel<<<(BN + 1023) / 1024, 1024>>>();
    count_kernel<<<BE / 256, 256>>>(edges);
    scan_local_kernel<<<NSCAN, SCAN_BLK>>>();
    scan_bsum_kernel<<<1, 64>>>();
    scan_add_kernel<<<NSCAN, SCAN_BLK>>>();
    scatter_kernel<<<BE / 256, 256>>>(edges);

    // Dense pipeline
    precompute_kernel<<<BN / 64, 256>>>(nodes, Wm);
    node_msg_kernel<<<BN / 8, 256>>>(ef, Wm, bm, ln_mg, ln_mb, msg_out);
    update_kernel<<<BN / 64, 256>>>(nodes, Wu, bu, ln_ug, ln_ub, upd_out);
}

// round 8
// speedup vs baseline: 1.3126x; 1.0166x over previous
#include <cuda_runtime.h>

// Problem constants
#define BB 8
#define NN 5000
#define EE 40000
#define FF 64
#define FEE 16
#define FIL 96
#define BN (BB*NN)      // 40000
#define BE (BB*EE)      // 320000
#define UPD_ELEMS (BN*FIL)   // 3,840,000
#define MSG_ELEMS (BE*FIL)   // 30,720,000
#define LN_EPS 1e-3f
#define SCAN_BLK 1024
#define NSCAN ((BN + SCAN_BLK - 1) / SCAN_BLK)   // 40 blocks

// Scratch (device globals: allocation-free per harness rules)
__device__ __align__(16) float g_Pa[UPD_ELEMS];   // nodes @ Wm[0:64]
__device__ __align__(16) float g_Pb[UPD_ELEMS];   // nodes @ Wm[64:128]
__device__ __align__(16) float g_agg[UPD_ELEMS];  // segment-sum of messages
__device__ int g_cnt[BN];        // per-node incoming-edge count
__device__ int g_off[BN + 1];    // CSR offsets
__device__ int g_slot[BE];       // per-edge slot within its node's list
__device__ int g_esrc[BE];       // CSR src list
__device__ int g_eid[BE];        // CSR edge id list
__device__ int g_bsum[NSCAN];    // per-block sums for hierarchical scan

__device__ __forceinline__ float warp_sum(float v) {
#pragma unroll
    for (int o = 16; o; o >>= 1) v += __shfl_xor_sync(0xffffffffu, v, o);
    return v;
}
__device__ __forceinline__ int warp_sum_i(int v) {
#pragma unroll
    for (int o = 16; o; o >>= 1) v += __shfl_xor_sync(0xffffffffu, v, o);
    return v;
}

// ---------------------------------------------------------------------------
// CSR step 1: zero counters.
// ---------------------------------------------------------------------------
__global__ void zero_cnt_kernel() {
    int i = blockIdx.x * 1024 + threadIdx.x;
    if (i < BN) g_cnt[i] = 0;
}

// ---------------------------------------------------------------------------
// CSR step 2: count incoming edges per node, record slot.
// ---------------------------------------------------------------------------
__global__ __launch_bounds__(256) void count_kernel(const int* __restrict__ edges) {
    int e = blockIdx.x * 256 + threadIdx.x;   // BE divisible by 256
    int2 e2 = ((const int2*)edges)[e];
    int node = (e / EE) * NN + e2.y;          // batch * NN + dst
    g_slot[e] = atomicAdd(&g_cnt[node], 1);
}

// ---------------------------------------------------------------------------
// CSR step 3a: per-block scan of g_cnt -> block-local offsets + block sums.
// ---------------------------------------------------------------------------
__global__ __launch_bounds__(SCAN_BLK) void scan_local_kernel() {
    __shared__ int wsum[32];
    int tid = threadIdx.x, lane = tid & 31, wid = tid >> 5;
    int i = blockIdx.x * SCAN_BLK + tid;
    int v = (i < BN) ? g_cnt[i] : 0;
    int incl = v;
#pragma unroll
    for (int d = 1; d < 32; d <<= 1) {
        int t = __shfl_up_sync(0xffffffffu, incl, d);
        if (lane >= d) incl += t;
    }
    if (lane == 31) wsum[wid] = incl;
    __syncthreads();
    if (wid == 0) {
        int w = wsum[lane];
        int ws = w;
#pragma unroll
        for (int d = 1; d < 32; d <<= 1) {
            int t = __shfl_up_sync(0xffffffffu, ws, d);
            if (lane >= d) ws += t;
        }
        wsum[lane] = ws - w;
        if (lane == 31) g_bsum[blockIdx.x] = ws;
    }
    __syncthreads();
    if (i < BN) g_off[i] = wsum[wid] + (incl - v);   // block-local exclusive
}

// ---------------------------------------------------------------------------
// CSR step 3b (merged): each block computes its own base = sum(g_bsum[0..bid))
// with one warp, then adds it. Last block writes g_off[BN].
// ---------------------------------------------------------------------------
__global__ __launch_bounds__(SCAN_BLK) void scan_add_kernel() {
    __shared__ int s_base;
    int tid = threadIdx.x;
    if (tid < 32) {
        int v = 0;
        for (int j = tid; j < blockIdx.x; j += 32) v += g_bsum[j];
        v = warp_sum_i(v);
        if (tid == 0) s_base = v;
    }
    __syncthreads();
    int i = blockIdx.x * SCAN_BLK + tid;
    if (i < BN) g_off[i] += s_base;
    if (blockIdx.x == gridDim.x - 1 && tid == 0) g_off[BN] = BE;
}

// ---------------------------------------------------------------------------
// CSR step 4: scatter edge ids + src into per-node lists.
// ---------------------------------------------------------------------------
__global__ __launch_bounds__(256) void scatter_kernel(const int* __restrict__ edges) {
    int e = blockIdx.x * 256 + threadIdx.x;
    int2 e2 = ((const int2*)edges)[e];
    int node = (e / EE) * NN + e2.y;
    int p = g_off[node] + g_slot[e];
    g_eid[p] = e;
    g_esrc[p] = e2.x;
}

// ---------------------------------------------------------------------------
// K1: Pa|Pb = nodes(40000x64) @ [Wm[0:64] | Wm[64:128]] (64x192)
// v3: W in smem as Wt4[k4][c][4] so each thread reads 4 consecutive k as one
// LDS.128 (16B-aligned, conflict-free phases); X rows read as broadcast
// LDS.128. Per 4 k-steps: 14 LDS vs 56 before.
// ---------------------------------------------------------------------------
__global__ __launch_bounds__(256) void precompute_kernel(
    const float* __restrict__ nodes, const float* __restrict__ Wm) {
    __shared__ __align__(16) float Xs[64][32];
    __shared__ __align__(16) float Wt4[8][192][4];   // [k4][c][kk]

    int tid = threadIdx.x;
    int tx = tid & 31, ty = tid >> 5;
    int row0 = blockIdx.x * 64;

    float acc[8][6];
#pragma unroll
    for (int i = 0; i < 8; i++)
#pragma unroll
        for (int j = 0; j < 6; j++) acc[i][j] = 0.0f;

    for (int t = 0; t < 2; t++) {
        __syncthreads();
        // W tile: 32x192, coalesced gmem read, STS into [k4][c][kk].
#pragma unroll
        for (int it = 0; it < 24; it++) {
            int idx = tid + 256 * it;
            int k = idx / 192, c = idx % 192;
            float v = (c < 96) ? Wm[(t * 32 + k) * FIL + c]
                               : Wm[(64 + t * 32 + k) * FIL + (c - 96)];
            Wt4[k >> 2][c][k & 3] = v;
        }
        // X tile: 64x32 floats = 512 float4, 2 per thread (coalesced).
#pragma unroll
        for (int it = 0; it < 2; it++) {
            int idx = tid + 256 * it;
            int r = idx >> 3, c4 = idx & 7;
            ((float4*)&Xs[r][0])[c4] =
                ((const float4*)(nodes + (row0 + r) * FF + t * 32))[c4];
        }
        __syncthreads();
#pragma unroll
        for (int k4 = 0; k4 < 8; k4++) {
            float4 wv[6];
#pragma unroll
            for (int j = 0; j < 6; j++)
                wv[j] = *(const float4*)&Wt4[k4][tx + 32 * j][0];
#pragma unroll
            for (int i = 0; i < 8; i++) {
                float4 xv = *(const float4*)&Xs[ty + 8 * i][4 * k4]; // broadcast
#pragma unroll
                for (int j = 0; j < 6; j++) {
                    acc[i][j] += xv.x * wv[j].x;
                    acc[i][j] += xv.y * wv[j].y;
                    acc[i][j] += xv.z * wv[j].z;
                    acc[i][j] += xv.w * wv[j].w;
                }
            }
        }
    }

#pragma unroll
    for (int i = 0; i < 8; i++) {
        int row = row0 + ty + 8 * i;
#pragma unroll
        for (int j = 0; j < 6; j++) {
            int c = tx + 32 * j;
            if (c < 96) g_Pa[row * FIL + c] = acc[i][j];
            else        g_Pb[row * FIL + (c - 96)] = acc[i][j];
        }
    }
}

// ---------------------------------------------------------------------------
// K2 (fused, proven R7): warp per destination node; compute message,
// write it, accumulate into registers, single store to g_agg. No atomics.
// ---------------------------------------------------------------------------
__global__ __launch_bounds__(256) void node_msg_kernel(
    const float* __restrict__ ef, const float* __restrict__ Wm,
    const float* __restrict__ bm, const float* __restrict__ gamma,
    const float* __restrict__ beta, float* __restrict__ msg_out) {
    __shared__ float WmC[16 * 96];  // Wm rows 128..143
    __shared__ float s_bm[96], s_g[96], s_b[96];

    int tid = threadIdx.x;
    for (int i = tid; i < 16 * 96; i += 256) WmC[i] = Wm[128 * FIL + i];
    if (tid < 96) { s_bm[tid] = bm[tid]; s_g[tid] = gamma[tid]; s_b[tid] = beta[tid]; }
    __syncthreads();

    int warp = tid >> 5, lane = tid & 31;
    int v = blockIdx.x * 8 + warp;   // BN divisible by 8
    int base = (v / NN) * NN;        // batch * NN

    int beg = g_off[v], end = g_off[v + 1];

    float pb0 = g_Pb[v * FIL + lane];
    float pb1 = g_Pb[v * FIL + lane + 32];
    float pb2 = g_Pb[v * FIL + lane + 64];

    float acc0 = 0.f, acc1 = 0.f, acc2 = 0.f;

    for (int c0 = beg; c0 < end; c0 += 32) {
        int m = min(32, end - c0);
        int e_l   = (lane < m) ? g_eid[c0 + lane]  : 0;
        int src_l = (lane < m) ? g_esrc[c0 + lane] : 0;

        for (int j = 0; j < m; j++) {
            int ej   = __shfl_sync(0xffffffffu, e_l, j);
            int srcj = __shfl_sync(0xffffffffu, src_l, j);

            float efv = (lane < 16) ? ef[ej * FEE + lane] : 0.0f;

            float a0 = s_bm[lane], a1 = s_bm[lane + 32], a2 = s_bm[lane + 64];
#pragma unroll
            for (int k = 0; k < 16; k++) {
                float x = __shfl_sync(0xffffffffu, efv, k);
                a0 += x * WmC[k * 96 + lane];
                a1 += x * WmC[k * 96 + lane + 32];
                a2 += x * WmC[k * 96 + lane + 64];
            }

            int pa_off = (base + srcj) * FIL;
            a0 += g_Pa[pa_off + lane]      + pb0;
            a1 += g_Pa[pa_off + lane + 32] + pb1;
            a2 += g_Pa[pa_off + lane + 64] + pb2;

            a0 = fmaxf(a0, 0.0f); a1 = fmaxf(a1, 0.0f); a2 = fmaxf(a2, 0.0f);

            float mean = warp_sum(a0 + a1 + a2) * (1.0f / 96.0f);
            float d0 = a0 - mean, d1 = a1 - mean, d2 = a2 - mean;
            float var = warp_sum(d0 * d0 + d1 * d1 + d2 * d2) * (1.0f / 96.0f);
            float inv = rsqrtf(var + LN_EPS);

            float y0 = d0 * inv * s_g[lane]      + s_b[lane];
            float y1 = d1 * inv * s_g[lane + 32] + s_b[lane + 32];
            float y2 = d2 * inv * s_g[lane + 64] + s_b[lane + 64];

            int mo = ej * FIL;
            msg_out[mo + lane]      = y0;
            msg_out[mo + lane + 32] = y1;
            msg_out[mo + lane + 64] = y2;

            acc0 += y0; acc1 += y1; acc2 += y2;
        }
    }

    int o = v * FIL;
    g_agg[o + lane]      = acc0;
    g_agg[o + lane + 32] = acc1;
    g_agg[o + lane + 64] = acc2;
}

// ---------------------------------------------------------------------------
// K3: updated = LN(relu([nodes | agg](40000x160) @ Wu(160x96) + bu))
// v3: same Wt4 smem layout -> 11 LDS per 4 k-steps (was 44).
// ---------------------------------------------------------------------------
__global__ __launch_bounds__(256) void update_kernel(
    const float* __restrict__ nodes, const float* __restrict__ Wu,
    const float* __restrict__ bu, const float* __restrict__ gamma,
    const float* __restrict__ beta, float* __restrict__ out) {
    __shared__ __align__(16) float Xs[64][32];
    __shared__ __align__(16) float Wt4[8][96][4];   // [k4][c][kk]
    __shared__ float s_bu[96], s_g[96], s_b[96];

    int tid = threadIdx.x;
    int tx = tid & 31, ty = tid >> 5;
    int row0 = blockIdx.x * 64;

    if (tid < 96) { s_bu[tid] = bu[tid]; s_g[tid] = gamma[tid]; s_b[tid] = beta[tid]; }
    __syncthreads();

    float acc[8][3];
#pragma unroll
    for (int i = 0; i < 8; i++) {
        acc[i][0] = s_bu[tx];
        acc[i][1] = s_bu[tx + 32];
        acc[i][2] = s_bu[tx + 64];
    }

    for (int t = 0; t < 5; t++) {
        __syncthreads();
#pragma unroll
        for (int it = 0; it < 12; it++) {
            int idx = tid + 256 * it;
            int k = idx / 96, c = idx % 96;
            Wt4[k >> 2][c][k & 3] = Wu[(t * 32 + k) * FIL + c];
        }
#pragma unroll
        for (int it = 0; it < 2; it++) {
            int idx = tid + 256 * it;
            int r = idx >> 3, c4 = idx & 7;
            float4 v;
            if (t < 2) v = ((const float4*)(nodes + (row0 + r) * FF + t * 32))[c4];
            else       v = ((const float4*)(g_agg + (row0 + r) * FIL + (t - 2) * 32))[c4];
            ((float4*)&Xs[r][0])[c4] = v;
        }
        __syncthreads();
#pragma unroll
        for (int k4 = 0; k4 < 8; k4++) {
            float4 w0 = *(const float4*)&Wt4[k4][tx][0];
            float4 w1 = *(const float4*)&Wt4[k4][tx + 32][0];
            float4 w2 = *(const float4*)&Wt4[k4][tx + 64][0];
#pragma unroll
            for (int i = 0; i < 8; i++) {
                float4 xv = *(const float4*)&Xs[ty + 8 * i][4 * k4]; // broadcast
                acc[i][0] += xv.x * w0.x + xv.y * w0.y + xv.z * w0.z + xv.w * w0.w;
                acc[i][1] += xv.x * w1.x + xv.y * w1.y + xv.z * w1.z + xv.w * w1.w;
                acc[i][2] += xv.x * w2.x + xv.y * w2.y + xv.z * w2.z + xv.w * w2.w;
            }
        }
    }

#pragma unroll
    for (int i = 0; i < 8; i++) {
        int row = row0 + ty + 8 * i;
        float v0 = fmaxf(acc[i][0], 0.0f);
        float v1 = fmaxf(acc[i][1], 0.0f);
        float v2 = fmaxf(acc[i][2], 0.0f);
        float mean = warp_sum(v0 + v1 + v2) * (1.0f / 96.0f);
        float d0 = v0 - mean, d1 = v1 - mean, d2 = v2 - mean;
        float var = warp_sum(d0 * d0 + d1 * d1 + d2 * d2) * (1.0f / 96.0f);
        float inv = rsqrtf(var + LN_EPS);
        int o = row * FIL;
        out[o + tx]      = d0 * inv * s_g[tx]      + s_b[tx];
        out[o + tx + 32] = d1 * inv * s_g[tx + 32] + s_b[tx + 32];
        out[o + tx + 64] = d2 * inv * s_g[tx + 64] + s_b[tx + 64];
    }
}

// ---------------------------------------------------------------------------
// Fork-join resources (created at static init: before any harness checkpoint
// or capture; no device-memory allocation inside kernel_launch itself).
// ---------------------------------------------------------------------------
static cudaStream_t g_s2;
static cudaEvent_t g_evFork, g_evJoin;
static struct StreamInit {
    StreamInit() {
        cudaStreamCreateWithFlags(&g_s2, cudaStreamNonBlocking);
        cudaEventCreateWithFlags(&g_evFork, cudaEventDisableTiming);
        cudaEventCreateWithFlags(&g_evJoin, cudaEventDisableTiming);
    }
} g_streamInit;

// ---------------------------------------------------------------------------
// Launch: [stream0: CSR chain] || [s2: precompute] -> node_msg -> update.
// ---------------------------------------------------------------------------
extern "C" void kernel_launch(void* const* d_in, const int* in_sizes, int n_in,
                              void* d_out, int out_size) {
    const float* nodes = (const float*)d_in[0];
    const float* ef    = (const float*)d_in[1];
    const int*   edges = (const int*)d_in[2];
    const float* Wm    = (const float*)d_in[3];
    const float* bm    = (const float*)d_in[4];
    const float* ln_mg = (const float*)d_in[5];
    const float* ln_mb = (const float*)d_in[6];
    const float* Wu    = (const float*)d_in[7];
    const float* bu    = (const float*)d_in[8];
    const float* ln_ug = (const float*)d_in[9];
    const float* ln_ub = (const float*)d_in[10];

    float* out = (float*)d_out;
    float* upd_out = out;                  // updated_nodes first (tuple order)
    float* msg_out = out + UPD_ELEMS;      // then messages

    // Fork: precompute on side stream, CSR chain on main stream.
    cudaEventRecord(g_evFork, 0);
    cudaStreamWaitEvent(g_s2, g_evFork, 0);
    precompute_kernel<<<BN / 64, 256, 0, g_s2>>>(nodes, Wm);
    cudaEventRecord(g_evJoin, g_s2);

    zero_cnt_kernel<<<(BN + 1023) / 1024, 1024>>>();
    count_kernel<<<BE / 256, 256>>>(edges);
    scan_local_kernel<<<NSCAN, SCAN_BLK>>>();
    scan_add_kernel<<<NSCAN, SCAN_BLK>>>();
    scatter_kernel<<<BE / 256, 256>>>(edges);

    // Join, then dense tail.
    cudaStreamWaitEvent(0, g_evJoin, 0);
    node_msg_kernel<<<BN / 8, 256>>>(ef, Wm, bm, ln_mg, ln_mb, msg_out);
    update_kernel<<<BN / 64, 256>>>(nodes, Wu, bu, ln_ug, ln_ub, upd_out);
}